// round 5
// baseline (speedup 1.0000x reference)
#include <cuda_runtime.h>
#include <math.h>

#define B 64
#define T 4096
#define D 512
#define NSPLIT 16                // CTAs per batch in partial kernel
#define WARPS 8                  // warps per CTA
#define NPART (NSPLIT * WARPS)   // 128 partials per batch
#define ROWS_PER_WARP 32         // T / NSPLIT / WARPS

// Scratch (static device globals: allocation-free)
__device__ float g_key[B * D];                       // 128 KB
__device__ float g_pm[B * NPART];
__device__ float g_ps[B * NPART];
__device__ float g_pc[(size_t)B * NPART * D];        // ~16.8 MB
__device__ int   g_mask_kind;                        // 0=int32, 1=uint8, 2=float32

// ---------------------------------------------------------------------------
// Kernel 1: k[b,d] = sum_j W[d,j]*q[b,j] + bias[d].  W read exactly ONCE.
// 64 CTAs x 8 warps; warp w owns W row d = blk*8+w held in registers,
// loops over all 64 batches (q rows hit L1 after first warp touches them).
// Block 0 additionally sniffs the mask dtype (idempotent atomicMax).
// ---------------------------------------------------------------------------
__global__ __launch_bounds__(256) void key_kernel(const float* __restrict__ q,
                                                  const float* __restrict__ W,
                                                  const float* __restrict__ bias,
                                                  const unsigned int* __restrict__ mw) {
    // --- mask dtype sniff (block 0 only, ~2048 words) ---
    if (blockIdx.x == 0) {
        int kind = 0;
        for (int i = threadIdx.x; i < 2048; i += blockDim.x) {
            unsigned int w = mw[i];
            if (w == 0x3f800000u)            kind = 2;   // float 1.0f
            else if ((w & 0xFFFFFF00u) != 0) kind = kind > 1 ? kind : 1; // high byte set
        }
        if (kind) atomicMax(&g_mask_kind, kind);   // stays 0 => int32
    }

    const int warp = threadIdx.x >> 5;
    const int lane = threadIdx.x & 31;
    const int d    = blockIdx.x * 8 + warp;

    // W row in registers: lane l holds cols {4l + 128j}
    float4 wf[4];
    const float* wr = W + (size_t)d * D + 4 * lane;
#pragma unroll
    for (int j = 0; j < 4; j++)
        wf[j] = *reinterpret_cast<const float4*>(wr + 128 * j);
    const float bd = bias[d];

    for (int b = 0; b < B; b++) {
        const float* qr = q + b * D + 4 * lane;
        float4 qv[4];
#pragma unroll
        for (int j = 0; j < 4; j++)
            qv[j] = *reinterpret_cast<const float4*>(qr + 128 * j);
        float p = 0.f;
#pragma unroll
        for (int j = 0; j < 4; j++) {
            p = fmaf(wf[j].x, qv[j].x, p);
            p = fmaf(wf[j].y, qv[j].y, p);
            p = fmaf(wf[j].z, qv[j].z, p);
            p = fmaf(wf[j].w, qv[j].w, p);
        }
#pragma unroll
        for (int off = 16; off > 0; off >>= 1)
            p += __shfl_xor_sync(0xffffffffu, p, off);
        if (lane == 0) g_key[b * D + d] = p + bd;
    }
}

// ---------------------------------------------------------------------------
// Kernel 2: per-warp online softmax over a 32-row strip, masked rows skipped.
// TWO independent softmax states (even/odd rows) to halve the serial
// shuffle/exp chain and double memory-level parallelism. All row-gating
// predicates are warp-uniform (derived from the ballot bitmap).
// ---------------------------------------------------------------------------
__global__ __launch_bounds__(256) void partial_kernel(const float* __restrict__ A,
                                                      const void* __restrict__ mask_raw) {
    const int b     = blockIdx.x / NSPLIT;
    const int split = blockIdx.x % NSPLIT;
    const int warp  = threadIdx.x >> 5;
    const int lane  = threadIdx.x & 31;
    const int t0    = split * (T / NSPLIT) + warp * ROWS_PER_WARP;

    const size_t midx = (size_t)(t0 + lane) * B + b;
    const int kind = g_mask_kind;
    bool masked;
    if (kind == 1)      masked = ((const unsigned char*)mask_raw)[midx] != 0;
    else if (kind == 0) masked = ((const int*)mask_raw)[midx] != 0;
    else                masked = ((const float*)mask_raw)[midx] != 0.f;
    const unsigned mvote = __ballot_sync(0xffffffffu, masked);

    float4 kf[4];
    const float* kb = g_key + b * D + 4 * lane;
#pragma unroll
    for (int j = 0; j < 4; j++)
        kf[j] = *reinterpret_cast<const float4*>(kb + 128 * j);

    float mA = -INFINITY, sA = 0.f, mB = -INFINITY, sB = 0.f;
    float4 cA[4], cB[4];
#pragma unroll
    for (int j = 0; j < 4; j++) {
        cA[j] = make_float4(0.f, 0.f, 0.f, 0.f);
        cB[j] = make_float4(0.f, 0.f, 0.f, 0.f);
    }

    const float* base = A + ((size_t)b * T + t0) * D + 4 * lane;

#pragma unroll 2
    for (int rp = 0; rp < ROWS_PER_WARP; rp += 2) {
        const bool doA = !((mvote >> rp) & 1u);       // warp-uniform
        const bool doB = !((mvote >> (rp + 1)) & 1u); // warp-uniform
        float4 aA[4], aB[4];
        const float* rowA = base + (size_t)rp * D;
        const float* rowB = rowA + D;
        if (doA) {
#pragma unroll
            for (int j = 0; j < 4; j++)
                aA[j] = *reinterpret_cast<const float4*>(rowA + 128 * j);
        }
        if (doB) {
#pragma unroll
            for (int j = 0; j < 4; j++)
                aB[j] = *reinterpret_cast<const float4*>(rowB + 128 * j);
        }

        float pA = 0.f, pB = 0.f;
        if (doA) {
#pragma unroll
            for (int j = 0; j < 4; j++) {
                pA = fmaf(aA[j].x, kf[j].x, pA);
                pA = fmaf(aA[j].y, kf[j].y, pA);
                pA = fmaf(aA[j].z, kf[j].z, pA);
                pA = fmaf(aA[j].w, kf[j].w, pA);
            }
        }
        if (doB) {
#pragma unroll
            for (int j = 0; j < 4; j++) {
                pB = fmaf(aB[j].x, kf[j].x, pB);
                pB = fmaf(aB[j].y, kf[j].y, pB);
                pB = fmaf(aB[j].z, kf[j].z, pB);
                pB = fmaf(aB[j].w, kf[j].w, pB);
            }
        }
        // two independent shuffle-reduce chains, interleaved
#pragma unroll
        for (int off = 16; off > 0; off >>= 1) {
            if (doA) pA += __shfl_xor_sync(0xffffffffu, pA, off);
            if (doB) pB += __shfl_xor_sync(0xffffffffu, pB, off);
        }

        if (doA) {
            float mn    = fmaxf(mA, pA);
            float alpha = __expf(mA - mn);   // mA=-inf -> 0
            float w     = __expf(pA - mn);
            sA = sA * alpha + w;
#pragma unroll
            for (int j = 0; j < 4; j++) {
                cA[j].x = fmaf(w, aA[j].x, cA[j].x * alpha);
                cA[j].y = fmaf(w, aA[j].y, cA[j].y * alpha);
                cA[j].z = fmaf(w, aA[j].z, cA[j].z * alpha);
                cA[j].w = fmaf(w, aA[j].w, cA[j].w * alpha);
            }
            mA = mn;
        }
        if (doB) {
            float mn    = fmaxf(mB, pB);
            float alpha = __expf(mB - mn);
            float w     = __expf(pB - mn);
            sB = sB * alpha + w;
#pragma unroll
            for (int j = 0; j < 4; j++) {
                cB[j].x = fmaf(w, aB[j].x, cB[j].x * alpha);
                cB[j].y = fmaf(w, aB[j].y, cB[j].y * alpha);
                cB[j].z = fmaf(w, aB[j].z, cB[j].z * alpha);
                cB[j].w = fmaf(w, aB[j].w, cB[j].w * alpha);
            }
            mB = mn;
        }
    }

    // merge states A and B (guard the all-masked case: both -inf)
    float m = fmaxf(mA, mB), s;
    if (m == -INFINITY) {
        s = 0.f;
#pragma unroll
        for (int j = 0; j < 4; j++) cA[j] = make_float4(0.f, 0.f, 0.f, 0.f);
    } else {
        float eA = (mA == -INFINITY) ? 0.f : __expf(mA - m);
        float eB = (mB == -INFINITY) ? 0.f : __expf(mB - m);
        s = sA * eA + sB * eB;
#pragma unroll
        for (int j = 0; j < 4; j++) {
            cA[j].x = cA[j].x * eA + cB[j].x * eB;
            cA[j].y = cA[j].y * eA + cB[j].y * eB;
            cA[j].z = cA[j].z * eA + cB[j].z * eB;
            cA[j].w = cA[j].w * eA + cB[j].w * eB;
        }
    }

    const int pid = blockIdx.x * WARPS + warp;
    if (lane == 0) {
        g_pm[pid] = m;
        g_ps[pid] = s;
    }
    float* pc = g_pc + (size_t)pid * D + 4 * lane;
#pragma unroll
    for (int j = 0; j < 4; j++)
        *reinterpret_cast<float4*>(pc + 128 * j) = cA[j];
}

// ---------------------------------------------------------------------------
// Kernel 3: combine 128 partials per batch.  256 CTAs (4 per batch), 128
// threads; each thread owns one of its CTA's 128 D-columns.
// ---------------------------------------------------------------------------
__global__ __launch_bounds__(128) void reduce_kernel(float* __restrict__ out) {
    const int b    = blockIdx.x >> 2;
    const int part = blockIdx.x & 3;
    const int tid  = threadIdx.x;

    __shared__ float sc[NPART];
    __shared__ float Msh, Ssh;

    sc[tid] = g_pm[b * NPART + tid];
    __syncthreads();
    if (tid == 0) {
        float mm = -INFINITY;
#pragma unroll 8
        for (int i = 0; i < NPART; i++) mm = fmaxf(mm, sc[i]);
        Msh = mm;
    }
    __syncthreads();
    {
        float mi = sc[tid];
        sc[tid] = (mi == -INFINITY) ? 0.f : __expf(mi - Msh);
    }
    __syncthreads();
    if (tid == 0) {
        float acc = 0.f;
#pragma unroll 8
        for (int i = 0; i < NPART; i++) acc += sc[i] * g_ps[b * NPART + i];
        Ssh = acc;
    }
    __syncthreads();

    const int d = part * 128 + tid;
    float acc = 0.f;
    const float* pc = g_pc + (size_t)b * NPART * D + d;
#pragma unroll 16
    for (int i = 0; i < NPART; i++)
        acc = fmaf(pc[(size_t)i * D], sc[i], acc);
    out[b * D + d] = acc / Ssh;
}

// ---------------------------------------------------------------------------
extern "C" void kernel_launch(void* const* d_in, const int* in_sizes, int n_in,
                              void* d_out, int out_size) {
    const float* q    = (const float*)d_in[0];   // [B, D]
    const float* A    = (const float*)d_in[1];   // [B, T, D]
    const void*  mask = d_in[2];                 // [T, B] bool-ish (dtype sniffed)
    const float* W    = (const float*)d_in[3];   // [D, D]
    const float* bias = (const float*)d_in[4];   // [D]
    float*       out  = (float*)d_out;           // [B, 1, D]

    key_kernel<<<64, 256>>>(q, W, bias, (const unsigned int*)mask);
    partial_kernel<<<B * NSPLIT, WARPS * 32>>>(A, mask);
    reduce_kernel<<<B * 4, 128>>>(out);
}

// round 6
// speedup vs baseline: 1.4726x; 1.4726x over previous
#include <cuda_runtime.h>
#include <math.h>

#define B 64
#define T 4096
#define D 512
#define NSPLIT 16                // CTAs per batch in partial kernel
#define WARPS 8                  // warps per CTA
#define NPART (NSPLIT * WARPS)   // 128 partials per batch
#define ROWS_PER_WARP 32         // T / NSPLIT / WARPS

#define KTB 8                    // key kernel: batches per CTA
#define KTD 32                   // key kernel: d-columns per CTA
#define QPITCH 516               // smem pitch in floats (conflict-free)

// Scratch (static device globals: allocation-free)
__device__ float g_key[B * D];                       // 128 KB
__device__ float g_pm[B * NPART];
__device__ float g_ps[B * NPART];
__device__ float g_pc[(size_t)B * NPART * D];        // ~16.8 MB
__device__ int   g_mask_kind;                        // 0=int32, 1=uint8, 2=float32

// ---------------------------------------------------------------------------
// Kernel 1: k[b,d] = sum_j W[d,j]*q[b,j] + bias[d].
// Tiled GEMM, one output per thread, no shuffles, no serial batch loop.
// Grid (D/KTD, B/KTB) = (16, 8) CTAs x 256 threads = 32768 = 64*512 outputs.
// Lane mapping inside warp w: d = bx*32 + w*4 + (lane>>3), b = by*8 + (lane&7)
//   -> W loads are 4-distinct-address broadcasts, q comes from smem
//      at pitch 516 floats (banks (4b)%32 => conflict-free LDS.128).
// Block (0,0) also sniffs the mask dtype (idempotent atomicMax).
// ---------------------------------------------------------------------------
__global__ __launch_bounds__(256) void key_kernel(const float* __restrict__ q,
                                                  const float* __restrict__ W,
                                                  const float* __restrict__ bias,
                                                  const unsigned int* __restrict__ mw) {
    if (blockIdx.x == 0 && blockIdx.y == 0) {
        int kind = 0;
        for (int i = threadIdx.x; i < 2048; i += blockDim.x) {
            unsigned int w = mw[i];
            if (w == 0x3f800000u)            kind = 2;                    // float 1.0f
            else if ((w & 0xFFFFFF00u) != 0) kind = kind > 1 ? kind : 1;  // high byte set
        }
        if (kind) atomicMax(&g_mask_kind, kind);   // stays 0 => int32
    }

    __shared__ float qs[KTB * QPITCH];

    const int b0 = blockIdx.y * KTB;
    const int d0 = blockIdx.x * KTD;

    // Stage q tile: KTB rows x 512 floats = 1024 float4; 256 threads x 4 each.
#pragma unroll
    for (int k = 0; k < 4; k++) {
        int idx = threadIdx.x + k * 256;          // float4 index in tile
        int row = idx >> 7;                       // / 128
        int col = idx & 127;                      // float4 col
        float4 v = reinterpret_cast<const float4*>(q + (size_t)(b0 + row) * D)[col];
        *reinterpret_cast<float4*>(&qs[row * QPITCH + col * 4]) = v;
    }
    __syncthreads();

    const int warp = threadIdx.x >> 5;
    const int lane = threadIdx.x & 31;
    const int d    = d0 + warp * 4 + (lane >> 3);
    const int bl   = lane & 7;

    const float4* wrow = reinterpret_cast<const float4*>(W + (size_t)d * D);
    const float*  qrow = &qs[bl * QPITCH];

    float a0 = 0.f, a1 = 0.f, a2 = 0.f, a3 = 0.f;
#pragma unroll 8
    for (int j = 0; j < D / 4; j++) {
        float4 wv = wrow[j];
        float4 qv = *reinterpret_cast<const float4*>(qrow + 4 * j);
        a0 = fmaf(wv.x, qv.x, a0);
        a1 = fmaf(wv.y, qv.y, a1);
        a2 = fmaf(wv.z, qv.z, a2);
        a3 = fmaf(wv.w, qv.w, a3);
    }
    g_key[(size_t)(b0 + bl) * D + d] = (a0 + a1) + (a2 + a3) + bias[d];
}

// ---------------------------------------------------------------------------
// Kernel 2: per-warp online softmax over a 32-row strip, masked rows skipped.
// Two independent softmax states (even/odd rows); A streamed with __ldcs so
// the 512MB tensor doesn't evict g_pc from L2. Row-gating predicates are
// warp-uniform (ballot bitmap).
// ---------------------------------------------------------------------------
__global__ __launch_bounds__(256) void partial_kernel(const float* __restrict__ A,
                                                      const void* __restrict__ mask_raw) {
    const int b     = blockIdx.x / NSPLIT;
    const int split = blockIdx.x % NSPLIT;
    const int warp  = threadIdx.x >> 5;
    const int lane  = threadIdx.x & 31;
    const int t0    = split * (T / NSPLIT) + warp * ROWS_PER_WARP;

    const size_t midx = (size_t)(t0 + lane) * B + b;
    const int kind = g_mask_kind;
    bool masked;
    if (kind == 1)      masked = ((const unsigned char*)mask_raw)[midx] != 0;
    else if (kind == 0) masked = ((const int*)mask_raw)[midx] != 0;
    else                masked = ((const float*)mask_raw)[midx] != 0.f;
    const unsigned mvote = __ballot_sync(0xffffffffu, masked);

    float4 kf[4];
    const float* kb = g_key + b * D + 4 * lane;
#pragma unroll
    for (int j = 0; j < 4; j++)
        kf[j] = *reinterpret_cast<const float4*>(kb + 128 * j);

    float mA = -INFINITY, sA = 0.f, mB = -INFINITY, sB = 0.f;
    float4 cA[4], cB[4];
#pragma unroll
    for (int j = 0; j < 4; j++) {
        cA[j] = make_float4(0.f, 0.f, 0.f, 0.f);
        cB[j] = make_float4(0.f, 0.f, 0.f, 0.f);
    }

    const float* base = A + ((size_t)b * T + t0) * D + 4 * lane;

#pragma unroll 2
    for (int rp = 0; rp < ROWS_PER_WARP; rp += 2) {
        const bool doA = !((mvote >> rp) & 1u);       // warp-uniform
        const bool doB = !((mvote >> (rp + 1)) & 1u); // warp-uniform
        float4 aA[4], aB[4];
        const float* rowA = base + (size_t)rp * D;
        const float* rowB = rowA + D;
        if (doA) {
#pragma unroll
            for (int j = 0; j < 4; j++)
                aA[j] = __ldcs(reinterpret_cast<const float4*>(rowA + 128 * j));
        }
        if (doB) {
#pragma unroll
            for (int j = 0; j < 4; j++)
                aB[j] = __ldcs(reinterpret_cast<const float4*>(rowB + 128 * j));
        }

        float pA = 0.f, pB = 0.f;
        if (doA) {
#pragma unroll
            for (int j = 0; j < 4; j++) {
                pA = fmaf(aA[j].x, kf[j].x, pA);
                pA = fmaf(aA[j].y, kf[j].y, pA);
                pA = fmaf(aA[j].z, kf[j].z, pA);
                pA = fmaf(aA[j].w, kf[j].w, pA);
            }
        }
        if (doB) {
#pragma unroll
            for (int j = 0; j < 4; j++) {
                pB = fmaf(aB[j].x, kf[j].x, pB);
                pB = fmaf(aB[j].y, kf[j].y, pB);
                pB = fmaf(aB[j].z, kf[j].z, pB);
                pB = fmaf(aB[j].w, kf[j].w, pB);
            }
        }
        // two independent shuffle-reduce chains, interleaved
#pragma unroll
        for (int off = 16; off > 0; off >>= 1) {
            if (doA) pA += __shfl_xor_sync(0xffffffffu, pA, off);
            if (doB) pB += __shfl_xor_sync(0xffffffffu, pB, off);
        }

        if (doA) {
            float mn    = fmaxf(mA, pA);
            float alpha = __expf(mA - mn);   // mA=-inf -> 0
            float w     = __expf(pA - mn);
            sA = sA * alpha + w;
#pragma unroll
            for (int j = 0; j < 4; j++) {
                cA[j].x = fmaf(w, aA[j].x, cA[j].x * alpha);
                cA[j].y = fmaf(w, aA[j].y, cA[j].y * alpha);
                cA[j].z = fmaf(w, aA[j].z, cA[j].z * alpha);
                cA[j].w = fmaf(w, aA[j].w, cA[j].w * alpha);
            }
            mA = mn;
        }
        if (doB) {
            float mn    = fmaxf(mB, pB);
            float alpha = __expf(mB - mn);
            float w     = __expf(pB - mn);
            sB = sB * alpha + w;
#pragma unroll
            for (int j = 0; j < 4; j++) {
                cB[j].x = fmaf(w, aB[j].x, cB[j].x * alpha);
                cB[j].y = fmaf(w, aB[j].y, cB[j].y * alpha);
                cB[j].z = fmaf(w, aB[j].z, cB[j].z * alpha);
                cB[j].w = fmaf(w, aB[j].w, cB[j].w * alpha);
            }
            mB = mn;
        }
    }

    // merge states A and B (guard the all-masked case: both -inf)
    float m = fmaxf(mA, mB), s;
    if (m == -INFINITY) {
        s = 0.f;
#pragma unroll
        for (int j = 0; j < 4; j++) cA[j] = make_float4(0.f, 0.f, 0.f, 0.f);
    } else {
        float eA = (mA == -INFINITY) ? 0.f : __expf(mA - m);
        float eB = (mB == -INFINITY) ? 0.f : __expf(mB - m);
        s = sA * eA + sB * eB;
#pragma unroll
        for (int j = 0; j < 4; j++) {
            cA[j].x = cA[j].x * eA + cB[j].x * eB;
            cA[j].y = cA[j].y * eA + cB[j].y * eB;
            cA[j].z = cA[j].z * eA + cB[j].z * eB;
            cA[j].w = cA[j].w * eA + cB[j].w * eB;
        }
    }

    const int pid = blockIdx.x * WARPS + warp;
    if (lane == 0) {
        g_pm[pid] = m;
        g_ps[pid] = s;
    }
    float* pc = g_pc + (size_t)pid * D + 4 * lane;
#pragma unroll
    for (int j = 0; j < 4; j++)
        *reinterpret_cast<float4*>(pc + 128 * j) = cA[j];
}

// ---------------------------------------------------------------------------
// Kernel 3: combine 128 partials per batch.  256 CTAs (4 per batch), 128
// threads; each thread owns one of its CTA's 128 D-columns.
// ---------------------------------------------------------------------------
__global__ __launch_bounds__(128) void reduce_kernel(float* __restrict__ out) {
    const int b    = blockIdx.x >> 2;
    const int part = blockIdx.x & 3;
    const int tid  = threadIdx.x;

    __shared__ float sc[NPART];
    __shared__ float Msh, Ssh;

    sc[tid] = g_pm[b * NPART + tid];
    __syncthreads();
    if (tid == 0) {
        float mm = -INFINITY;
#pragma unroll 8
        for (int i = 0; i < NPART; i++) mm = fmaxf(mm, sc[i]);
        Msh = mm;
    }
    __syncthreads();
    {
        float mi = sc[tid];
        sc[tid] = (mi == -INFINITY) ? 0.f : __expf(mi - Msh);
    }
    __syncthreads();
    if (tid == 0) {
        float acc = 0.f;
#pragma unroll 8
        for (int i = 0; i < NPART; i++) acc += sc[i] * g_ps[b * NPART + i];
        Ssh = acc;
    }
    __syncthreads();

    const int d = part * 128 + tid;
    float acc = 0.f;
    const float* pc = g_pc + (size_t)b * NPART * D + d;
#pragma unroll 16
    for (int i = 0; i < NPART; i++)
        acc = fmaf(pc[(size_t)i * D], sc[i], acc);
    out[b * D + d] = acc / Ssh;
}

// ---------------------------------------------------------------------------
extern "C" void kernel_launch(void* const* d_in, const int* in_sizes, int n_in,
                              void* d_out, int out_size) {
    const float* q    = (const float*)d_in[0];   // [B, D]
    const float* A    = (const float*)d_in[1];   // [B, T, D]
    const void*  mask = d_in[2];                 // [T, B] bool-ish (dtype sniffed)
    const float* W    = (const float*)d_in[3];   // [D, D]
    const float* bias = (const float*)d_in[4];   // [D]
    float*       out  = (float*)d_out;           // [B, 1, D]

    key_kernel<<<dim3(D / KTD, B / KTB), 256>>>(q, W, bias, (const unsigned int*)mask);
    partial_kernel<<<B * NSPLIT, WARPS * 32>>>(A, mask);
    reduce_kernel<<<B * 4, 128>>>(out);
}

// round 7
// speedup vs baseline: 1.6575x; 1.1256x over previous
#include <cuda_runtime.h>
#include <math.h>

#define B 64
#define T 4096
#define D 512
#define NSPLIT 32                // CTAs per batch in partial kernel
#define WARPS 4                  // warps per CTA (128 threads)
#define NPART (NSPLIT * WARPS)   // 128 partials per batch
#define ROWS_PER_WARP 32         // (T/NSPLIT)/WARPS = 128/4

#define KTB 8                    // key kernel: batches per CTA
#define KTD 32                   // key kernel: d-columns per CTA
#define QPITCH 516               // smem pitch in floats (conflict-free)

// Scratch (static device globals: allocation-free)
__device__ float g_key[B * D];                       // 128 KB
__device__ float g_pm[B * NPART];
__device__ float g_ps[B * NPART];
__device__ float g_pc[(size_t)B * NPART * D];        // ~16.8 MB
__device__ int   g_mask_kind;                        // 0=int32, 1=uint8, 2=float32

// ---------------------------------------------------------------------------
// Kernel 1: k[b,d] = sum_j W[d,j]*q[b,j] + bias[d].
// One output per thread; inner loop chunked into batches of 8 independent
// float4 W loads staged in registers (forces MLP=8; R6 profile showed the
// 32-reg build at MLP~2, pure L2-latency-bound at 0.9% DRAM / 7.4% issue).
// Block (0,0) also sniffs the mask dtype (idempotent atomicMax).
// ---------------------------------------------------------------------------
__global__ __launch_bounds__(256) void key_kernel(const float* __restrict__ q,
                                                  const float* __restrict__ W,
                                                  const float* __restrict__ bias,
                                                  const unsigned int* __restrict__ mw) {
    if (blockIdx.x == 0 && blockIdx.y == 0) {
        int kind = 0;
        for (int i = threadIdx.x; i < 2048; i += blockDim.x) {
            unsigned int w = mw[i];
            if (w == 0x3f800000u)            kind = 2;                    // float 1.0f
            else if ((w & 0xFFFFFF00u) != 0) kind = kind > 1 ? kind : 1;  // high byte set
        }
        if (kind) atomicMax(&g_mask_kind, kind);   // stays 0 => int32
    }

    __shared__ float qs[KTB * QPITCH];

    const int b0 = blockIdx.y * KTB;
    const int d0 = blockIdx.x * KTD;

    // Stage q tile: KTB rows x 512 floats = 1024 float4; 256 threads x 4 each.
#pragma unroll
    for (int k = 0; k < 4; k++) {
        int idx = threadIdx.x + k * 256;
        int row = idx >> 7;
        int col = idx & 127;
        float4 v = reinterpret_cast<const float4*>(q + (size_t)(b0 + row) * D)[col];
        *reinterpret_cast<float4*>(&qs[row * QPITCH + col * 4]) = v;
    }
    __syncthreads();

    const int warp = threadIdx.x >> 5;
    const int lane = threadIdx.x & 31;
    const int d    = d0 + warp * 4 + (lane >> 3);
    const int bl   = lane & 7;

    const float4* wrow  = reinterpret_cast<const float4*>(W + (size_t)d * D);
    const float4* qrow4 = reinterpret_cast<const float4*>(&qs[bl * QPITCH]);

    float a0 = 0.f, a1 = 0.f, a2 = 0.f, a3 = 0.f;
#pragma unroll
    for (int ch = 0; ch < (D / 4) / 8; ch++) {      // 16 chunks of 8 float4
        float4 wv[8];
#pragma unroll
        for (int u = 0; u < 8; u++) wv[u] = wrow[ch * 8 + u];   // 8 LDGs in flight
#pragma unroll
        for (int u = 0; u < 8; u++) {
            float4 qv = qrow4[ch * 8 + u];
            a0 = fmaf(wv[u].x, qv.x, a0);
            a1 = fmaf(wv[u].y, qv.y, a1);
            a2 = fmaf(wv[u].z, qv.z, a2);
            a3 = fmaf(wv[u].w, qv.w, a3);
        }
    }
    g_key[(size_t)(b0 + bl) * D + d] = (a0 + a1) + (a2 + a3) + bias[d];
}

// ---------------------------------------------------------------------------
// Kernel 2: per-warp online softmax over a 32-row strip, masked rows skipped.
// 128-thread CTAs (4 warps) for higher occupancy (3-4 CTAs/SM at ~110 regs
// vs 1 at 256 threads); 2048 CTAs balance better over 148 SMs.
// Two independent softmax states (even/odd rows); unroll 4 lets ptxas hoist
// the next pairs' loads across the shuffle chains. A streamed with __ldcs.
// ---------------------------------------------------------------------------
__global__ __launch_bounds__(128) void partial_kernel(const float* __restrict__ A,
                                                      const void* __restrict__ mask_raw) {
    const int b     = blockIdx.x / NSPLIT;
    const int split = blockIdx.x % NSPLIT;
    const int warp  = threadIdx.x >> 5;
    const int lane  = threadIdx.x & 31;
    const int t0    = split * (T / NSPLIT) + warp * ROWS_PER_WARP;

    const size_t midx = (size_t)(t0 + lane) * B + b;
    const int kind = g_mask_kind;
    bool masked;
    if (kind == 1)      masked = ((const unsigned char*)mask_raw)[midx] != 0;
    else if (kind == 0) masked = ((const int*)mask_raw)[midx] != 0;
    else                masked = ((const float*)mask_raw)[midx] != 0.f;
    const unsigned mvote = __ballot_sync(0xffffffffu, masked);

    float4 kf[4];
    const float* kb = g_key + b * D + 4 * lane;
#pragma unroll
    for (int j = 0; j < 4; j++)
        kf[j] = *reinterpret_cast<const float4*>(kb + 128 * j);

    float mA = -INFINITY, sA = 0.f, mB = -INFINITY, sB = 0.f;
    float4 cA[4], cB[4];
#pragma unroll
    for (int j = 0; j < 4; j++) {
        cA[j] = make_float4(0.f, 0.f, 0.f, 0.f);
        cB[j] = make_float4(0.f, 0.f, 0.f, 0.f);
    }

    const float* base = A + ((size_t)b * T + t0) * D + 4 * lane;

#pragma unroll 4
    for (int rp = 0; rp < ROWS_PER_WARP; rp += 2) {
        const bool doA = !((mvote >> rp) & 1u);       // warp-uniform
        const bool doB = !((mvote >> (rp + 1)) & 1u); // warp-uniform
        float4 aA[4], aB[4];
        const float* rowA = base + (size_t)rp * D;
        const float* rowB = rowA + D;
        if (doA) {
#pragma unroll
            for (int j = 0; j < 4; j++)
                aA[j] = __ldcs(reinterpret_cast<const float4*>(rowA + 128 * j));
        }
        if (doB) {
#pragma unroll
            for (int j = 0; j < 4; j++)
                aB[j] = __ldcs(reinterpret_cast<const float4*>(rowB + 128 * j));
        }

        float pA = 0.f, pB = 0.f;
        if (doA) {
#pragma unroll
            for (int j = 0; j < 4; j++) {
                pA = fmaf(aA[j].x, kf[j].x, pA);
                pA = fmaf(aA[j].y, kf[j].y, pA);
                pA = fmaf(aA[j].z, kf[j].z, pA);
                pA = fmaf(aA[j].w, kf[j].w, pA);
            }
        }
        if (doB) {
#pragma unroll
            for (int j = 0; j < 4; j++) {
                pB = fmaf(aB[j].x, kf[j].x, pB);
                pB = fmaf(aB[j].y, kf[j].y, pB);
                pB = fmaf(aB[j].z, kf[j].z, pB);
                pB = fmaf(aB[j].w, kf[j].w, pB);
            }
        }
#pragma unroll
        for (int off = 16; off > 0; off >>= 1) {
            if (doA) pA += __shfl_xor_sync(0xffffffffu, pA, off);
            if (doB) pB += __shfl_xor_sync(0xffffffffu, pB, off);
        }

        if (doA) {
            float mn    = fmaxf(mA, pA);
            float alpha = __expf(mA - mn);   // mA=-inf -> 0
            float w     = __expf(pA - mn);
            sA = sA * alpha + w;
#pragma unroll
            for (int j = 0; j < 4; j++) {
                cA[j].x = fmaf(w, aA[j].x, cA[j].x * alpha);
                cA[j].y = fmaf(w, aA[j].y, cA[j].y * alpha);
                cA[j].z = fmaf(w, aA[j].z, cA[j].z * alpha);
                cA[j].w = fmaf(w, aA[j].w, cA[j].w * alpha);
            }
            mA = mn;
        }
        if (doB) {
            float mn    = fmaxf(mB, pB);
            float alpha = __expf(mB - mn);
            float w     = __expf(pB - mn);
            sB = sB * alpha + w;
#pragma unroll
            for (int j = 0; j < 4; j++) {
                cB[j].x = fmaf(w, aB[j].x, cB[j].x * alpha);
                cB[j].y = fmaf(w, aB[j].y, cB[j].y * alpha);
                cB[j].z = fmaf(w, aB[j].z, cB[j].z * alpha);
                cB[j].w = fmaf(w, aB[j].w, cB[j].w * alpha);
            }
            mB = mn;
        }
    }

    // merge states A and B (guard the all-masked case: both -inf)
    float m = fmaxf(mA, mB), s;
    if (m == -INFINITY) {
        s = 0.f;
#pragma unroll
        for (int j = 0; j < 4; j++) cA[j] = make_float4(0.f, 0.f, 0.f, 0.f);
    } else {
        float eA = (mA == -INFINITY) ? 0.f : __expf(mA - m);
        float eB = (mB == -INFINITY) ? 0.f : __expf(mB - m);
        s = sA * eA + sB * eB;
#pragma unroll
        for (int j = 0; j < 4; j++) {
            cA[j].x = cA[j].x * eA + cB[j].x * eB;
            cA[j].y = cA[j].y * eA + cB[j].y * eB;
            cA[j].z = cA[j].z * eA + cB[j].z * eB;
            cA[j].w = cA[j].w * eA + cB[j].w * eB;
        }
    }

    const int pid = blockIdx.x * WARPS + warp;   // = b*NPART + split*WARPS + warp
    if (lane == 0) {
        g_pm[pid] = m;
        g_ps[pid] = s;
    }
    float* pc = g_pc + (size_t)pid * D + 4 * lane;
#pragma unroll
    for (int j = 0; j < 4; j++)
        *reinterpret_cast<float4*>(pc + 128 * j) = cA[j];
}

// ---------------------------------------------------------------------------
// Kernel 3: combine 128 partials per batch.  256 CTAs (4 per batch), 128
// threads; each thread owns one of its CTA's 128 D-columns.
// ---------------------------------------------------------------------------
__global__ __launch_bounds__(128) void reduce_kernel(float* __restrict__ out) {
    const int b    = blockIdx.x >> 2;
    const int part = blockIdx.x & 3;
    const int tid  = threadIdx.x;

    __shared__ float sc[NPART];
    __shared__ float Msh, Ssh;

    sc[tid] = g_pm[b * NPART + tid];
    __syncthreads();
    if (tid == 0) {
        float mm = -INFINITY;
#pragma unroll 8
        for (int i = 0; i < NPART; i++) mm = fmaxf(mm, sc[i]);
        Msh = mm;
    }
    __syncthreads();
    {
        float mi = sc[tid];
        sc[tid] = (mi == -INFINITY) ? 0.f : __expf(mi - Msh);
    }
    __syncthreads();
    if (tid == 0) {
        float acc = 0.f;
#pragma unroll 8
        for (int i = 0; i < NPART; i++) acc += sc[i] * g_ps[b * NPART + i];
        Ssh = acc;
    }
    __syncthreads();

    const int d = part * 128 + tid;
    float acc = 0.f;
    const float* pc = g_pc + (size_t)b * NPART * D + d;
#pragma unroll 16
    for (int i = 0; i < NPART; i++)
        acc = fmaf(pc[(size_t)i * D], sc[i], acc);
    out[b * D + d] = acc / Ssh;
}

// ---------------------------------------------------------------------------
extern "C" void kernel_launch(void* const* d_in, const int* in_sizes, int n_in,
                              void* d_out, int out_size) {
    const float* q    = (const float*)d_in[0];   // [B, D]
    const float* A    = (const float*)d_in[1];   // [B, T, D]
    const void*  mask = d_in[2];                 // [T, B] bool-ish (dtype sniffed)
    const float* W    = (const float*)d_in[3];   // [D, D]
    const float* bias = (const float*)d_in[4];   // [D]
    float*       out  = (float*)d_out;           // [B, 1, D]

    key_kernel<<<dim3(D / KTD, B / KTB), 256>>>(q, W, bias, (const unsigned int*)mask);
    partial_kernel<<<B * NSPLIT, WARPS * 32>>>(A, mask);
    reduce_kernel<<<B * 4, 128>>>(out);
}

// round 10
// speedup vs baseline: 1.8680x; 1.1270x over previous
#include <cuda_runtime.h>
#include <math.h>

#define B 64
#define T 4096
#define D 512
#define NSPLIT 32                // CTAs per batch in partial kernel
#define WARPS 4                  // warps per CTA (128 threads)
#define NPART NSPLIT             // ONE partial per CTA (warps merged in smem)
#define ROWS_PER_WARP 32         // (T/NSPLIT)/WARPS

#define KTB 8                    // key kernel: batches per CTA
#define KTD 32                   // key kernel: d-columns per CTA
#define KZ  4                    // key kernel: split-K factor
#define KSLICE (D / KZ)          // 128 floats per K slice
#define QPITCH 132               // smem pitch (floats) for the 128-float q slice

// Scratch (static device globals: allocation-free)
__device__ float g_kpart[KZ * B * D];                // 512 KB (split-K partials)
__device__ float g_pm[B * NPART];
__device__ float g_ps[B * NPART];
__device__ float g_pc[(size_t)B * NPART * D];        // 4.2 MB
__device__ int   g_mask_kind;                        // 0=int32, 1=uint8, 2=float32

// ---------------------------------------------------------------------------
// Kernel 1: split-K key GEMM.  kpart[z][b,d] = sum_{j in slice z} W[d,j]*q[b,j]
// (+ bias on z=0).  Grid (16,8,4) x 256 = 131072 threads (~28 warps/SM) so
// L2 latency is hidden by occupancy, not per-thread MLP (R7: 32K threads,
// 6.9 warps/SM, 14.4us latency-bound at 1.1% DRAM).
// Block (0,0,0) also sniffs the mask dtype (idempotent atomicMax).
// ---------------------------------------------------------------------------
__global__ __launch_bounds__(256) void key_kernel(const float* __restrict__ q,
                                                  const float* __restrict__ W,
                                                  const float* __restrict__ bias,
                                                  const unsigned int* __restrict__ mw) {
    if (blockIdx.x == 0 && blockIdx.y == 0 && blockIdx.z == 0) {
        int kind = 0;
        for (int i = threadIdx.x; i < 2048; i += blockDim.x) {
            unsigned int w = mw[i];
            if (w == 0x3f800000u)            kind = 2;                    // float 1.0f
            else if ((w & 0xFFFFFF00u) != 0) kind = kind > 1 ? kind : 1;  // high byte set
        }
        if (kind) atomicMax(&g_mask_kind, kind);   // stays 0 => int32
    }

    __shared__ float qs[KTB * QPITCH];

    const int b0 = blockIdx.y * KTB;
    const int d0 = blockIdx.x * KTD;
    const int k0 = blockIdx.z * KSLICE;

    // Stage q slice: 8 rows x 128 floats = 256 float4; one per thread.
    {
        int row = threadIdx.x >> 5;               // 32 float4 per row
        int col = threadIdx.x & 31;
        float4 v = *reinterpret_cast<const float4*>(q + (size_t)(b0 + row) * D + k0 + 4 * col);
        *reinterpret_cast<float4*>(&qs[row * QPITCH + 4 * col]) = v;
    }
    __syncthreads();

    const int warp = threadIdx.x >> 5;
    const int lane = threadIdx.x & 31;
    const int d    = d0 + warp * 4 + (lane >> 3);
    const int bl   = lane & 7;

    const float4* wrow  = reinterpret_cast<const float4*>(W + (size_t)d * D + k0);
    const float4* qrow4 = reinterpret_cast<const float4*>(&qs[bl * QPITCH]);

    float a0 = 0.f, a1 = 0.f, a2 = 0.f, a3 = 0.f;
#pragma unroll
    for (int j = 0; j < KSLICE / 4; j++) {        // 32 float4
        float4 wv = wrow[j];
        float4 qv = qrow4[j];
        a0 = fmaf(wv.x, qv.x, a0);
        a1 = fmaf(wv.y, qv.y, a1);
        a2 = fmaf(wv.z, qv.z, a2);
        a3 = fmaf(wv.w, qv.w, a3);
    }
    float r = (a0 + a1) + (a2 + a3);
    if (blockIdx.z == 0) r += bias[d];
    g_kpart[blockIdx.z * (B * D) + (size_t)(b0 + bl) * D + d] = r;
}

// ---------------------------------------------------------------------------
// Kernel 2: per-warp online softmax over a 32-row strip, masked rows skipped;
// the 4 warp states are then merged in smem -> ONE partial per CTA (g_pc
// traffic 16.8MB -> 4.2MB each way). k fragment is the sum of the 4 split-K
// slices (L2-hit loads). A streamed with __ldcs.
// ---------------------------------------------------------------------------
__global__ __launch_bounds__(128) void partial_kernel(const float* __restrict__ A,
                                                      const void* __restrict__ mask_raw) {
    const int b     = blockIdx.x / NSPLIT;
    const int split = blockIdx.x % NSPLIT;
    const int warp  = threadIdx.x >> 5;
    const int lane  = threadIdx.x & 31;
    const int t0    = split * (T / NSPLIT) + warp * ROWS_PER_WARP;

    const size_t midx = (size_t)(t0 + lane) * B + b;
    const int kind = g_mask_kind;
    bool masked;
    if (kind == 1)      masked = ((const unsigned char*)mask_raw)[midx] != 0;
    else if (kind == 0) masked = ((const int*)mask_raw)[midx] != 0;
    else                masked = ((const float*)mask_raw)[midx] != 0.f;
    const unsigned mvote = __ballot_sync(0xffffffffu, masked);

    // k fragment: sum the 4 split-K slices (deterministic order)
    float4 kf[4];
#pragma unroll
    for (int j = 0; j < 4; j++) {
        const float* kb = g_kpart + (size_t)b * D + 4 * lane + 128 * j;
        float4 s = *reinterpret_cast<const float4*>(kb);
#pragma unroll
        for (int z = 1; z < KZ; z++) {
            float4 t = *reinterpret_cast<const float4*>(kb + (size_t)z * B * D);
            s.x += t.x; s.y += t.y; s.z += t.z; s.w += t.w;
        }
        kf[j] = s;
    }

    float mA = -INFINITY, sA = 0.f, mB = -INFINITY, sB = 0.f;
    float4 cA[4], cB[4];
#pragma unroll
    for (int j = 0; j < 4; j++) {
        cA[j] = make_float4(0.f, 0.f, 0.f, 0.f);
        cB[j] = make_float4(0.f, 0.f, 0.f, 0.f);
    }

    const float* base = A + ((size_t)b * T + t0) * D + 4 * lane;

#pragma unroll 4
    for (int rp = 0; rp < ROWS_PER_WARP; rp += 2) {
        const bool doA = !((mvote >> rp) & 1u);       // warp-uniform
        const bool doB = !((mvote >> (rp + 1)) & 1u); // warp-uniform
        float4 aA[4], aB[4];
        const float* rowA = base + (size_t)rp * D;
        const float* rowB = rowA + D;
        if (doA) {
#pragma unroll
            for (int j = 0; j < 4; j++)
                aA[j] = __ldcs(reinterpret_cast<const float4*>(rowA + 128 * j));
        }
        if (doB) {
#pragma unroll
            for (int j = 0; j < 4; j++)
                aB[j] = __ldcs(reinterpret_cast<const float4*>(rowB + 128 * j));
        }

        float pA = 0.f, pB = 0.f;
        if (doA) {
#pragma unroll
            for (int j = 0; j < 4; j++) {
                pA = fmaf(aA[j].x, kf[j].x, pA);
                pA = fmaf(aA[j].y, kf[j].y, pA);
                pA = fmaf(aA[j].z, kf[j].z, pA);
                pA = fmaf(aA[j].w, kf[j].w, pA);
            }
        }
        if (doB) {
#pragma unroll
            for (int j = 0; j < 4; j++) {
                pB = fmaf(aB[j].x, kf[j].x, pB);
                pB = fmaf(aB[j].y, kf[j].y, pB);
                pB = fmaf(aB[j].z, kf[j].z, pB);
                pB = fmaf(aB[j].w, kf[j].w, pB);
            }
        }
#pragma unroll
        for (int off = 16; off > 0; off >>= 1) {
            if (doA) pA += __shfl_xor_sync(0xffffffffu, pA, off);
            if (doB) pB += __shfl_xor_sync(0xffffffffu, pB, off);
        }

        if (doA) {
            float mn    = fmaxf(mA, pA);
            float alpha = __expf(mA - mn);   // mA=-inf -> 0
            float w     = __expf(pA - mn);
            sA = sA * alpha + w;
#pragma unroll
            for (int j = 0; j < 4; j++) {
                cA[j].x = fmaf(w, aA[j].x, cA[j].x * alpha);
                cA[j].y = fmaf(w, aA[j].y, cA[j].y * alpha);
                cA[j].z = fmaf(w, aA[j].z, cA[j].z * alpha);
                cA[j].w = fmaf(w, aA[j].w, cA[j].w * alpha);
            }
            mA = mn;
        }
        if (doB) {
            float mn    = fmaxf(mB, pB);
            float alpha = __expf(mB - mn);
            float w     = __expf(pB - mn);
            sB = sB * alpha + w;
#pragma unroll
            for (int j = 0; j < 4; j++) {
                cB[j].x = fmaf(w, aB[j].x, cB[j].x * alpha);
                cB[j].y = fmaf(w, aB[j].y, cB[j].y * alpha);
                cB[j].z = fmaf(w, aB[j].z, cB[j].z * alpha);
                cB[j].w = fmaf(w, aB[j].w, cB[j].w * alpha);
            }
            mB = mn;
        }
    }

    // merge states A and B within the warp (guard all-masked: both -inf)
    float m = fmaxf(mA, mB), s;
    if (m == -INFINITY) {
        s = 0.f;
#pragma unroll
        for (int j = 0; j < 4; j++) cA[j] = make_float4(0.f, 0.f, 0.f, 0.f);
    } else {
        float eA = (mA == -INFINITY) ? 0.f : __expf(mA - m);
        float eB = (mB == -INFINITY) ? 0.f : __expf(mB - m);
        s = sA * eA + sB * eB;
#pragma unroll
        for (int j = 0; j < 4; j++) {
            cA[j].x = cA[j].x * eA + cB[j].x * eB;
            cA[j].y = cA[j].y * eA + cB[j].y * eB;
            cA[j].z = cA[j].z * eA + cB[j].z * eB;
            cA[j].w = cA[j].w * eA + cB[j].w * eB;
        }
    }

    // ---- CTA-level merge of the 4 warp states (smem) ----
    __shared__ float sm_m[WARPS], sm_s[WARPS];
    __shared__ float sm_c[WARPS][D];
    if (lane == 0) { sm_m[warp] = m; sm_s[warp] = s; }
    __syncthreads();
    const float M = fmaxf(fmaxf(sm_m[0], sm_m[1]), fmaxf(sm_m[2], sm_m[3]));
    const float myscale = (m == -INFINITY) ? 0.f : __expf(m - M);
    float* cw = &sm_c[warp][4 * lane];
#pragma unroll
    for (int j = 0; j < 4; j++) {
        float4 v = cA[j];
        v.x *= myscale; v.y *= myscale; v.z *= myscale; v.w *= myscale;
        *reinterpret_cast<float4*>(cw + 128 * j) = v;
    }
    __syncthreads();

    const int pid = blockIdx.x;   // b*NSPLIT + split
    if (threadIdx.x == 0) {
        float st = 0.f;
#pragma unroll
        for (int w = 0; w < WARPS; w++) {
            float sc = (sm_m[w] == -INFINITY) ? 0.f : __expf(sm_m[w] - M);
            st += sm_s[w] * sc;
        }
        g_pm[pid] = M;
        g_ps[pid] = st;
    }
    float* pc = g_pc + (size_t)pid * D;
#pragma unroll
    for (int j = 0; j < 4; j++) {
        int col = threadIdx.x + 128 * j;
        pc[col] = ((sm_c[0][col] + sm_c[1][col]) + (sm_c[2][col] + sm_c[3][col]));
    }
}

// ---------------------------------------------------------------------------
// Kernel 3: combine 32 partials per batch.  256 CTAs (4 per batch), 128
// threads; each thread owns one of its CTA's 128 D-columns.
// ---------------------------------------------------------------------------
__global__ __launch_bounds__(128) void reduce_kernel(float* __restrict__ out) {
    const int b    = blockIdx.x >> 2;
    const int part = blockIdx.x & 3;
    const int tid  = threadIdx.x;

    __shared__ float sc[NPART];
    __shared__ float Msh, Ssh;

    if (tid < NPART) sc[tid] = g_pm[b * NPART + tid];
    __syncthreads();
    if (tid == 0) {
        float mm = -INFINITY;
#pragma unroll
        for (int i = 0; i < NPART; i++) mm = fmaxf(mm, sc[i]);
        Msh = mm;
    }
    __syncthreads();
    if (tid < NPART) {
        float mi = sc[tid];
        sc[tid] = (mi == -INFINITY) ? 0.f : __expf(mi - Msh);
    }
    __syncthreads();
    if (tid == 0) {
        float acc = 0.f;
#pragma unroll
        for (int i = 0; i < NPART; i++) acc += sc[i] * g_ps[b * NPART + i];
        Ssh = acc;
    }
    __syncthreads();

    const int d = part * 128 + tid;
    float acc = 0.f;
    const float* pc = g_pc + (size_t)b * NPART * D + d;
#pragma unroll
    for (int i = 0; i < NPART; i++)
        acc = fmaf(pc[(size_t)i * D], sc[i], acc);
    out[b * D + d] = acc / Ssh;
}

// ---------------------------------------------------------------------------
extern "C" void kernel_launch(void* const* d_in, const int* in_sizes, int n_in,
                              void* d_out, int out_size) {
    const float* q    = (const float*)d_in[0];   // [B, D]
    const float* A    = (const float*)d_in[1];   // [B, T, D]
    const void*  mask = d_in[2];                 // [T, B] bool-ish (dtype sniffed)
    const float* W    = (const float*)d_in[3];   // [D, D]
    const float* bias = (const float*)d_in[4];   // [D]
    float*       out  = (float*)d_out;           // [B, 1, D]

    key_kernel<<<dim3(D / KTD, B / KTB, KZ), 256>>>(q, W, bias, (const unsigned int*)mask);
    partial_kernel<<<B * NSPLIT, WARPS * 32>>>(A, mask);
    reduce_kernel<<<B * 4, 128>>>(out);
}